// round 8
// baseline (speedup 1.0000x reference)
#include <cuda_runtime.h>
#include <cuda_fp16.h>
#include <math.h>
#include <stdint.h>

#define BATCH 8
#define SEQ   4096
#define HID   256
#define NF    6

// Precombined per-batch weights, TRANSPOSED to [b][n][h], fp16.
__device__ __half g_B[BATCH * HID * HID];   // 1 MB

// ===========================================================================
// Helpers
// ===========================================================================
__device__ __forceinline__ uint32_t smem_u32(const void* p) {
    uint32_t a;
    asm("{ .reg .u64 t; cvta.to.shared.u64 t, %1; cvt.u32.u64 %0, t; }" : "=r"(a) : "l"(p));
    return a;
}
__device__ __forceinline__ void cp_async16(uint32_t dst, const void* src) {
    asm volatile("cp.async.ca.shared.global [%0], [%1], 16;" :: "r"(dst), "l"(src));
}
#define CP_COMMIT()  asm volatile("cp.async.commit_group;" ::: "memory")
#define CP_WAIT(n)   asm volatile("cp.async.wait_group %0;" :: "n"(n) : "memory")

__device__ __forceinline__ void ldmx4(uint32_t a, uint32_t r[4]) {
    asm volatile("ldmatrix.sync.aligned.m8n8.x4.shared.b16 {%0,%1,%2,%3}, [%4];"
                 : "=r"(r[0]), "=r"(r[1]), "=r"(r[2]), "=r"(r[3]) : "r"(a));
}
__device__ __forceinline__ void ldmx2(uint32_t a, uint32_t r[2]) {
    asm volatile("ldmatrix.sync.aligned.m8n8.x2.shared.b16 {%0,%1}, [%2];"
                 : "=r"(r[0]), "=r"(r[1]) : "r"(a));
}
__device__ __forceinline__ void mma16816(float c[4], const uint32_t a[4], const uint32_t b[2]) {
    asm volatile(
        "mma.sync.aligned.m16n8k16.row.col.f32.f16.f16.f32 "
        "{%0,%1,%2,%3},{%4,%5,%6,%7},{%8,%9},{%0,%1,%2,%3};"
        : "+f"(c[0]), "+f"(c[1]), "+f"(c[2]), "+f"(c[3])
        : "r"(a[0]), "r"(a[1]), "r"(a[2]), "r"(a[3]), "r"(b[0]), "r"(b[1]));
}

// Swizzled byte offset inside a [rows][64 fp16] tile (128B rows, XOR swizzle)
__device__ __forceinline__ uint32_t sw_off(int r, int k) {
    int c = k >> 3;
    return (uint32_t)((r << 7) + ((c ^ (r & 7)) << 4) + ((k & 7) << 1));
}

// ===========================================================================
// Kernel 1: build combined weights, transposed, fp16. grid (32, 8), 256 thr.
//   g_B[b][n][h] = fp16( sum_f W[f][h][n] * sin(freq_f*t_b + phase[f][n]) )
// ===========================================================================
__global__ __launch_bounds__(256) void build_M_kernel(
    const float* __restrict__ W,      // [F, H, H]
    const float* __restrict__ phase,  // [F, H]
    const float* __restrict__ t)      // [B, 1]
{
    __shared__ __half s_hi[8][HID];

    const int b  = blockIdx.y;
    const int h0 = blockIdx.x * 8;
    const int k  = threadIdx.x;
    const float tb = t[b];
    const float freqs[NF] = {1.f, 2.f, 4.f, 8.f, 7.f, 5.f};
    float res[NF];
#pragma unroll
    for (int f = 0; f < NF; f++) res[f] = sinf(freqs[f] * tb + phase[f * HID + k]);

#pragma unroll
    for (int hl = 0; hl < 8; hl++) {
        float acc = 0.f;
#pragma unroll
        for (int f = 0; f < NF; f++)
            acc = fmaf(W[((size_t)f * HID + h0 + hl) * HID + k], res[f], acc);
        s_hi[hl][k] = __float2half_rn(acc);
    }
    __syncthreads();

    const int n = k;
    __half th[8];
#pragma unroll
    for (int j = 0; j < 8; j++) th[j] = s_hi[j][n];
    *(uint4*)&g_B[((size_t)b * HID + n) * HID + h0] = *(uint4*)th;
}

// ===========================================================================
// Kernel 2: fp16 mma.sync GEMM, B-stationary.
// CTA: col strip of 128 n, 2 row tiles of 128 m, K=256 (4 chunks of 64).
// B strip (64 KB) loaded once via cp.async; A streamed LDG fp32 -> fp16 STS
// into a 2-stage ring, 8-chunk continuous pipeline. 256 thr, 2 CTAs/SM.
// ===========================================================================
#define OFF_B      0                  // 4 chunk-tiles x 16 KB
#define OFF_A      65536              // 2 stages x 16 KB
#define SMEM_TOTAL (65536 + 32768)    // 96 KB

__global__ __launch_bounds__(256, 2) void gemm_kernel(
    const float* __restrict__ X,   // [B, SEQ, HID]
    float* __restrict__ Y)         // [B, SEQ, HID]
{
    extern __shared__ char smem[];
    const uint32_t sb = smem_u32(smem);
    const int tid  = threadIdx.x;
    const int wid  = tid >> 5;
    const int lane = tid & 31;
    const int b    = blockIdx.z;
    const int row0 = blockIdx.y * 256;
    const int col0 = blockIdx.x * 128;

    // 8 warps: 2 (m) x 4 (n); warp tile 64 rows x 32 cols
    const int wm = (wid & 1) * 64;
    const int wn = (wid >> 1) * 32;

    const float*  A32 = X   + ((size_t)b * SEQ + row0) * HID;
    const __half* Bg  = g_B + ((size_t)b * HID + col0) * HID;
    float*        C   = Y   + ((size_t)b * SEQ + row0) * HID + col0;

    float acc[4][4][4];
#pragma unroll
    for (int i = 0; i < 4; i++)
#pragma unroll
        for (int j = 0; j < 4; j++)
#pragma unroll
            for (int q = 0; q < 4; q++) acc[i][j][q] = 0.f;

    // ---- B: enqueue all 4 chunk-tiles (one commit group per chunk)
    {
        const int lr = tid >> 3;   // 0..31
        const int lc = tid & 7;
#pragma unroll
        for (int c = 0; c < 4; c++) {
#pragma unroll
            for (int i = 0; i < 4; i++) {
                int r = lr + i * 32;
                uint32_t o = (uint32_t)(c * 16384) +
                             (uint32_t)((r << 7) + ((lc ^ (r & 7)) << 4));
                cp_async16(sb + OFF_B + o, &Bg[(size_t)r * HID + c * 64 + lc * 8]);
            }
            CP_COMMIT();
        }
    }

    // ---- A loader: chunk = 128 rows x 64 k fp32. thread -> row tid>>1,
    //      k-half (tid&1)*32; two rounds of 4 float4 to cap live registers.
    const int ar  = tid >> 1;
    const int ak0 = (tid & 1) * 32;

#define LOAD_A(stage, tilebase, kk)                                             \
    do {                                                                        \
        const float* ap = (tilebase) + (size_t)ar * HID + (kk) + ak0;           \
        _Pragma("unroll")                                                       \
        for (int h2 = 0; h2 < 2; h2++) {                                        \
            float4 v[4];                                                        \
            _Pragma("unroll")                                                   \
            for (int i = 0; i < 4; i++) v[i] = *(const float4*)&ap[h2 * 16 + i * 4]; \
            _Pragma("unroll")                                                   \
            for (int i = 0; i < 4; i++) {                                       \
                __half2 h01 = __floats2half2_rn(v[i].x, v[i].y);                \
                __half2 h23 = __floats2half2_rn(v[i].z, v[i].w);                \
                uint2 p; p.x = *(uint32_t*)&h01; p.y = *(uint32_t*)&h23;        \
                *(uint2*)(smem + OFF_A + (uint32_t)(stage) * 16384 +            \
                          sw_off(ar, ak0 + h2 * 16 + i * 4)) = p;               \
            }                                                                   \
        }                                                                       \
    } while (0)

#define COMPUTE(stage, bchunk)                                                  \
    do {                                                                        \
        const uint32_t aoff = sb + OFF_A + (uint32_t)(stage) * 16384;           \
        const uint32_t boff = sb + OFF_B + (uint32_t)(bchunk) * 16384;          \
        _Pragma("unroll")                                                       \
        for (int s = 0; s < 4; s++) {                                           \
            uint32_t ah[4][4], bh[4][2];                                        \
            const int arow = wm + (lane & 15);                                  \
            const int akk  = s * 16 + ((lane >> 4) << 3);                       \
            _Pragma("unroll")                                                   \
            for (int mi = 0; mi < 4; mi++)                                      \
                ldmx4(aoff + sw_off(arow + mi * 16, akk), ah[mi]);              \
            const int bkk = s * 16 + ((lane >> 3) & 1) * 8;                     \
            _Pragma("unroll")                                                   \
            for (int nj = 0; nj < 4; nj++)                                      \
                ldmx2(boff + sw_off(wn + nj * 8 + (lane & 7), bkk), bh[nj]);    \
            _Pragma("unroll")                                                   \
            for (int mi = 0; mi < 4; mi++)                                      \
                _Pragma("unroll")                                               \
                for (int nj = 0; nj < 4; nj++)                                  \
                    mma16816(acc[mi][nj], ah[mi], bh[nj]);                      \
        }                                                                       \
    } while (0)

#define EPILOGUE(tile)                                                          \
    do {                                                                        \
        float* Ct = C + (size_t)(tile) * 128 * HID;                             \
        _Pragma("unroll")                                                       \
        for (int mi = 0; mi < 4; mi++) {                                        \
            int r0 = wm + mi * 16 + (lane >> 2);                                \
            _Pragma("unroll")                                                   \
            for (int nj = 0; nj < 4; nj++) {                                    \
                int cc = wn + nj * 8 + (lane & 3) * 2;                          \
                *(float2*)&Ct[(size_t)r0 * HID + cc] =                          \
                    make_float2(acc[mi][nj][0], acc[mi][nj][1]);                \
                *(float2*)&Ct[(size_t)(r0 + 8) * HID + cc] =                    \
                    make_float2(acc[mi][nj][2], acc[mi][nj][3]);                \
                acc[mi][nj][0] = acc[mi][nj][1] = 0.f;                          \
                acc[mi][nj][2] = acc[mi][nj][3] = 0.f;                          \
            }                                                                   \
        }                                                                       \
    } while (0)

    // ---- prologue: A chunk 0 (tile 0) into stage 0
    LOAD_A(0, A32, 0);
    CP_WAIT(3);             // B chunk 0 resident
    __syncthreads();

    // ---- 8-chunk continuous pipeline (j = tile*4 + chunk)
    // j: compute stage j&1 / B chunk j&3; prefetch chunk j+1 into stage (j+1)&1
    LOAD_A(1, A32, 64);                    COMPUTE(0, 0); __syncthreads();   // j=0
    LOAD_A(0, A32, 128);  CP_WAIT(2);      COMPUTE(1, 1); __syncthreads();   // j=1
    LOAD_A(1, A32, 192);  CP_WAIT(1);      COMPUTE(0, 2); __syncthreads();   // j=2
    LOAD_A(0, A32 + 128 * HID, 0);
                          CP_WAIT(0);      COMPUTE(1, 3);
    EPILOGUE(0);                                          __syncthreads();   // j=3
    LOAD_A(1, A32 + 128 * HID, 64);        COMPUTE(0, 0); __syncthreads();   // j=4
    LOAD_A(0, A32 + 128 * HID, 128);       COMPUTE(1, 1); __syncthreads();   // j=5
    LOAD_A(1, A32 + 128 * HID, 192);       COMPUTE(0, 2); __syncthreads();   // j=6
                                           COMPUTE(1, 3);                    // j=7
    EPILOGUE(1);

#undef LOAD_A
#undef COMPUTE
#undef EPILOGUE
}

// ===========================================================================
extern "C" void kernel_launch(void* const* d_in, const int* in_sizes, int n_in,
                              void* d_out, int out_size) {
    const float* x     = (const float*)d_in[0];  // [8, 4096, 256]
    const float* t     = (const float*)d_in[1];  // [8, 1]
    const float* osc   = (const float*)d_in[2];  // [6, 256, 256]
    const float* phase = (const float*)d_in[3];  // [6, 256]
    float* out = (float*)d_out;                  // [8, 4096, 256]
    (void)in_sizes; (void)n_in; (void)out_size;

    cudaFuncSetAttribute(gemm_kernel, cudaFuncAttributeMaxDynamicSharedMemorySize, SMEM_TOTAL);

    build_M_kernel<<<dim3(32, BATCH), 256>>>(osc, phase, t);
    gemm_kernel<<<dim3(2, SEQ / 256, BATCH), 256, SMEM_TOTAL>>>(x, out);
}

// round 9
// speedup vs baseline: 1.1311x; 1.1311x over previous
#include <cuda_runtime.h>
#include <cuda_fp16.h>
#include <math.h>
#include <stdint.h>

#define BATCH 8
#define SEQ   4096
#define HID   256
#define NF    6

// Precombined per-batch weights, TRANSPOSED to [b][n][h], fp16.
__device__ __half g_B[BATCH * HID * HID];   // 1 MB
// x pre-converted to fp16
__device__ __half g_Ah[BATCH * SEQ * HID];  // 16 MB

// ===========================================================================
// Helpers
// ===========================================================================
__device__ __forceinline__ uint32_t smem_u32(const void* p) {
    uint32_t a;
    asm("{ .reg .u64 t; cvta.to.shared.u64 t, %1; cvt.u32.u64 %0, t; }" : "=r"(a) : "l"(p));
    return a;
}
__device__ __forceinline__ void cp_async16(uint32_t dst, const void* src) {
    asm volatile("cp.async.ca.shared.global [%0], [%1], 16;" :: "r"(dst), "l"(src));
}
#define CP_COMMIT()  asm volatile("cp.async.commit_group;" ::: "memory")
#define CP_WAIT(n)   asm volatile("cp.async.wait_group %0;" :: "n"(n) : "memory")

__device__ __forceinline__ void ldmx4(uint32_t a, uint32_t r[4]) {
    asm volatile("ldmatrix.sync.aligned.m8n8.x4.shared.b16 {%0,%1,%2,%3}, [%4];"
                 : "=r"(r[0]), "=r"(r[1]), "=r"(r[2]), "=r"(r[3]) : "r"(a));
}
__device__ __forceinline__ void mma16816(float c[4], const uint32_t a[4], const uint32_t b[2]) {
    asm volatile(
        "mma.sync.aligned.m16n8k16.row.col.f32.f16.f16.f32 "
        "{%0,%1,%2,%3},{%4,%5,%6,%7},{%8,%9},{%0,%1,%2,%3};"
        : "+f"(c[0]), "+f"(c[1]), "+f"(c[2]), "+f"(c[3])
        : "r"(a[0]), "r"(a[1]), "r"(a[2]), "r"(a[3]), "r"(b[0]), "r"(b[1]));
}

// Swizzled byte offset inside a [rows][64 fp16] tile (128B rows, XOR swizzle)
__device__ __forceinline__ uint32_t sw_off(int r, int k) {
    int c = k >> 3;
    return (uint32_t)((r << 7) + ((c ^ (r & 7)) << 4) + ((k & 7) << 1));
}

// ===========================================================================
// Kernel 0: convert x -> fp16 (streaming, 16 floats/thread for ILP).
// grid = 8*4096*256 / (256*16) = 2048 blocks.
// ===========================================================================
__global__ __launch_bounds__(256) void convert_A_kernel(
    const float* __restrict__ X, __half* __restrict__ Ah)
{
    size_t base = ((size_t)blockIdx.x * 256 + threadIdx.x) * 16;
    float4 v[4];
#pragma unroll
    for (int i = 0; i < 4; i++) v[i] = *(const float4*)&X[base + i * 4];
    uint4 o[2];
#pragma unroll
    for (int i = 0; i < 2; i++) {
        __half2 h0 = __floats2half2_rn(v[2*i].x,   v[2*i].y);
        __half2 h1 = __floats2half2_rn(v[2*i].z,   v[2*i].w);
        __half2 h2 = __floats2half2_rn(v[2*i+1].x, v[2*i+1].y);
        __half2 h3 = __floats2half2_rn(v[2*i+1].z, v[2*i+1].w);
        o[i].x = *(uint32_t*)&h0; o[i].y = *(uint32_t*)&h1;
        o[i].z = *(uint32_t*)&h2; o[i].w = *(uint32_t*)&h3;
    }
    *(uint4*)&Ah[base]     = o[0];
    *(uint4*)&Ah[base + 8] = o[1];
}

// ===========================================================================
// Kernel 1: build combined weights, transposed, fp16. grid (32, 8), 256 thr.
//   g_B[b][n][h] = fp16( sum_f W[f][h][n] * sin(freq_f*t_b + phase[f][n]) )
// ===========================================================================
__global__ __launch_bounds__(256) void build_M_kernel(
    const float* __restrict__ W,      // [F, H, H]
    const float* __restrict__ phase,  // [F, H]
    const float* __restrict__ t)      // [B, 1]
{
    __shared__ __half s_hi[8][HID];

    const int b  = blockIdx.y;
    const int h0 = blockIdx.x * 8;
    const int k  = threadIdx.x;
    const float tb = t[b];
    const float freqs[NF] = {1.f, 2.f, 4.f, 8.f, 7.f, 5.f};
    float res[NF];
#pragma unroll
    for (int f = 0; f < NF; f++) res[f] = sinf(freqs[f] * tb + phase[f * HID + k]);

#pragma unroll
    for (int hl = 0; hl < 8; hl++) {
        float acc = 0.f;
#pragma unroll
        for (int f = 0; f < NF; f++)
            acc = fmaf(W[((size_t)f * HID + h0 + hl) * HID + k], res[f], acc);
        s_hi[hl][k] = __float2half_rn(acc);
    }
    __syncthreads();

    const int n = k;
    __half th[8];
#pragma unroll
    for (int j = 0; j < 8; j++) th[j] = s_hi[j][n];
    *(uint4*)&g_B[((size_t)b * HID + n) * HID + h0] = *(uint4*)th;
}

// ===========================================================================
// Kernel 2: fp16 mma.sync GEMM, 128x128 tile, 256 thr, 2 CTAs/SM.
// Pure cp.async pipeline: 3 stages x (A 16KB + B 16KB) = 96 KB.
// K=256 in 4 chunks of 64.
// ===========================================================================
#define STAGE_SZ   32768
#define SMEM_TOTAL (3 * STAGE_SZ)   // 96 KB

__global__ __launch_bounds__(256, 2) void gemm_kernel(
    const __half* __restrict__ Ag,  // [B, SEQ, HID] fp16
    float* __restrict__ Y)          // [B, SEQ, HID]
{
    extern __shared__ char smem[];
    const uint32_t sb = smem_u32(smem);
    const int tid  = threadIdx.x;
    const int wid  = tid >> 5;
    const int lane = tid & 31;
    const int b    = blockIdx.z;
    const int row0 = blockIdx.y * 128;
    const int col0 = blockIdx.x * 128;

    // 8 warps: 2 (m) x 4 (n); warp tile 64 rows x 32 cols
    const int wm = (wid & 1) * 64;
    const int wn = (wid >> 1) * 32;

    const __half* A  = Ag  + ((size_t)b * SEQ + row0) * HID;
    const __half* Bg = g_B + ((size_t)b * HID + col0) * HID;

    float acc[4][4][4];
#pragma unroll
    for (int i = 0; i < 4; i++)
#pragma unroll
        for (int j = 0; j < 4; j++)
#pragma unroll
            for (int q = 0; q < 4; q++) acc[i][j][q] = 0.f;

    // Loaders (both panels 128 rows x 64 halves = 128B/row):
    // A: thread -> row tid>>1, half tid&1 (4 x 16B)
    const int arr = tid >> 1, aq = (tid & 1) * 32;
    // B: thread -> rows tid>>3 + 32i, chunk tid&7
    const int blr = tid >> 3, blc = tid & 7;

#define ISSUE(stage, kk)                                                        \
    do {                                                                        \
        const uint32_t st = sb + (uint32_t)(stage) * STAGE_SZ;                  \
        _Pragma("unroll")                                                       \
        for (int i = 0; i < 4; i++)                                             \
            cp_async16(st + sw_off(arr, aq + i * 8),                            \
                       &A[(size_t)arr * HID + (kk) + aq + i * 8]);              \
        _Pragma("unroll")                                                       \
        for (int i = 0; i < 4; i++) {                                           \
            int r = blr + i * 32;                                               \
            cp_async16(st + 16384 + sw_off(r, blc * 8),                         \
                       &Bg[(size_t)r * HID + (kk) + blc * 8]);                  \
        }                                                                       \
        CP_COMMIT();                                                            \
    } while (0)

#define COMPUTE(stage)                                                          \
    do {                                                                        \
        const uint32_t aoff = sb + (uint32_t)(stage) * STAGE_SZ;                \
        const uint32_t boff = aoff + 16384;                                     \
        _Pragma("unroll")                                                       \
        for (int s = 0; s < 4; s++) {                                           \
            uint32_t ah[4][4], bb[2][4];                                        \
            const int arow = wm + (lane & 15);                                  \
            const int akk  = s * 16 + ((lane >> 4) << 3);                       \
            _Pragma("unroll")                                                   \
            for (int mi = 0; mi < 4; mi++)                                      \
                ldmx4(aoff + sw_off(arow + mi * 16, akk), ah[mi]);              \
            const int bm  = lane >> 3;                                          \
            const int brq = ((bm >> 1) << 3) + (lane & 7);                      \
            const int bkq = s * 16 + ((bm & 1) << 3);                           \
            _Pragma("unroll")                                                   \
            for (int p = 0; p < 2; p++)                                         \
                ldmx4(boff + sw_off(wn + p * 16 + brq, bkq), bb[p]);            \
            _Pragma("unroll")                                                   \
            for (int mi = 0; mi < 4; mi++)                                      \
                _Pragma("unroll")                                               \
                for (int p = 0; p < 2; p++) {                                   \
                    mma16816(acc[mi][p * 2 + 0], ah[mi], &bb[p][0]);            \
                    mma16816(acc[mi][p * 2 + 1], ah[mi], &bb[p][2]);            \
                }                                                               \
        }                                                                       \
    } while (0)

    // ---- pipeline: stages 0..2 prefetched, chunk3 reuses stage 0
    ISSUE(0, 0);
    ISSUE(1, 64);
    ISSUE(2, 128);

    CP_WAIT(2); __syncthreads();
    COMPUTE(0);
    __syncthreads();          // stage 0 free
    ISSUE(0, 192);

    CP_WAIT(2); __syncthreads();
    COMPUTE(1);

    CP_WAIT(1); __syncthreads();
    COMPUTE(2);

    CP_WAIT(0); __syncthreads();
    COMPUTE(0);

    // ---- epilogue
    float* C = Y + ((size_t)b * SEQ + row0) * HID + col0;
#pragma unroll
    for (int mi = 0; mi < 4; mi++) {
        int r0 = wm + mi * 16 + (lane >> 2);
#pragma unroll
        for (int nj = 0; nj < 4; nj++) {
            int cc = wn + nj * 8 + (lane & 3) * 2;
            *(float2*)&C[(size_t)r0 * HID + cc]       = make_float2(acc[mi][nj][0], acc[mi][nj][1]);
            *(float2*)&C[(size_t)(r0 + 8) * HID + cc] = make_float2(acc[mi][nj][2], acc[mi][nj][3]);
        }
    }
#undef ISSUE
#undef COMPUTE
}

// ===========================================================================
extern "C" void kernel_launch(void* const* d_in, const int* in_sizes, int n_in,
                              void* d_out, int out_size) {
    const float* x     = (const float*)d_in[0];  // [8, 4096, 256]
    const float* t     = (const float*)d_in[1];  // [8, 1]
    const float* osc   = (const float*)d_in[2];  // [6, 256, 256]
    const float* phase = (const float*)d_in[3];  // [6, 256]
    float* out = (float*)d_out;                  // [8, 4096, 256]
    (void)in_sizes; (void)n_in; (void)out_size;

    cudaFuncSetAttribute(gemm_kernel, cudaFuncAttributeMaxDynamicSharedMemorySize, SMEM_TOTAL);

    __half* ah;
    cudaGetSymbolAddress((void**)&ah, g_Ah);

    convert_A_kernel<<<BATCH * SEQ * HID / (256 * 16), 256>>>(x, ah);
    build_M_kernel<<<dim3(32, BATCH), 256>>>(osc, phase, t);
    gemm_kernel<<<dim3(2, SEQ / 128, BATCH), 256, SMEM_TOTAL>>>(ah, out);
}

// round 10
// speedup vs baseline: 1.2791x; 1.1309x over previous
#include <cuda_runtime.h>
#include <cuda_fp16.h>
#include <math.h>
#include <stdint.h>

#define BATCH 8
#define SEQ   4096
#define HID   256
#define NF    6

// Precombined per-batch weights, TRANSPOSED to [b][n][h], fp16.
__device__ __half g_B[BATCH * HID * HID];   // 1 MB (L2-resident)

// ===========================================================================
// Helpers
// ===========================================================================
__device__ __forceinline__ uint32_t smem_u32(const void* p) {
    uint32_t a;
    asm("{ .reg .u64 t; cvta.to.shared.u64 t, %1; cvt.u32.u64 %0, t; }" : "=r"(a) : "l"(p));
    return a;
}
__device__ __forceinline__ void cp_async16(uint32_t dst, const void* src) {
    asm volatile("cp.async.ca.shared.global [%0], [%1], 16;" :: "r"(dst), "l"(src));
}
#define CP_COMMIT()  asm volatile("cp.async.commit_group;" ::: "memory")
#define CP_WAIT(n)   asm volatile("cp.async.wait_group %0;" :: "n"(n) : "memory")

__device__ __forceinline__ void ldmx4(uint32_t a, uint32_t r[4]) {
    asm volatile("ldmatrix.sync.aligned.m8n8.x4.shared.b16 {%0,%1,%2,%3}, [%4];"
                 : "=r"(r[0]), "=r"(r[1]), "=r"(r[2]), "=r"(r[3]) : "r"(a));
}
__device__ __forceinline__ void mma16816(float c[4], const uint32_t a[4], const uint32_t b[2]) {
    asm volatile(
        "mma.sync.aligned.m16n8k16.row.col.f32.f16.f16.f32 "
        "{%0,%1,%2,%3},{%4,%5,%6,%7},{%8,%9},{%0,%1,%2,%3};"
        : "+f"(c[0]), "+f"(c[1]), "+f"(c[2]), "+f"(c[3])
        : "r"(a[0]), "r"(a[1]), "r"(a[2]), "r"(a[3]), "r"(b[0]), "r"(b[1]));
}

// Swizzled byte offset inside a [rows][64 fp16] tile (128B rows, XOR swizzle)
__device__ __forceinline__ uint32_t sw_off(int r, int k) {
    int c = k >> 3;
    return (uint32_t)((r << 7) + ((c ^ (r & 7)) << 4) + ((k & 7) << 1));
}

// ===========================================================================
// Kernel 1: build combined weights, transposed, fp16. grid (32, 8), 256 thr.
//   g_B[b][n][h] = fp16( sum_f W[f][h][n] * sin(freq_f*t_b + phase[f][n]) )
// ===========================================================================
__global__ __launch_bounds__(256) void build_M_kernel(
    const float* __restrict__ W,      // [F, H, H]
    const float* __restrict__ phase,  // [F, H]
    const float* __restrict__ t)      // [B, 1]
{
    __shared__ __half s_hi[8][HID];

    const int b  = blockIdx.y;
    const int h0 = blockIdx.x * 8;
    const int k  = threadIdx.x;
    const float tb = t[b];
    const float freqs[NF] = {1.f, 2.f, 4.f, 8.f, 7.f, 5.f};
    float res[NF];
#pragma unroll
    for (int f = 0; f < NF; f++) res[f] = sinf(freqs[f] * tb + phase[f * HID + k]);

#pragma unroll
    for (int hl = 0; hl < 8; hl++) {
        float acc = 0.f;
#pragma unroll
        for (int f = 0; f < NF; f++)
            acc = fmaf(W[((size_t)f * HID + h0 + hl) * HID + k], res[f], acc);
        s_hi[hl][k] = __float2half_rn(acc);
    }
    __syncthreads();

    const int n = k;
    __half th[8];
#pragma unroll
    for (int j = 0; j < 8; j++) th[j] = s_hi[j][n];
    *(uint4*)&g_B[((size_t)b * HID + n) * HID + h0] = *(uint4*)th;
}

// ===========================================================================
// Kernel 2: fused fp16 mma.sync GEMM. CTA = 128 rows x FULL 256 cols in two
// 128-col strips over smem-resident A. x read ONCE (fp32 -> fp16 in prologue,
// 64 KB A panel). B: 8 chunks (2 strips x 4 k-chunks), 2x16KB double-buffer
// cp.async (L2-resident). 256 threads, 2 CTAs/SM. grid (32, 8).
// ===========================================================================
#define OFF_A      0                   // 4 chunk-tiles x 16 KB
#define OFF_B      65536               // 2 stages x 16 KB
#define SMEM_TOTAL (65536 + 32768)     // 96 KB

__global__ __launch_bounds__(256, 2) void gemm_kernel(
    const float* __restrict__ X,   // [B, SEQ, HID]
    float* __restrict__ Y)         // [B, SEQ, HID]
{
    extern __shared__ char smem[];
    const uint32_t sb = smem_u32(smem);
    const int tid  = threadIdx.x;
    const int wid  = tid >> 5;
    const int lane = tid & 31;
    const int b    = blockIdx.y;
    const int row0 = blockIdx.x * 128;

    // 8 warps: 2 (m) x 4 (n); warp tile 64 rows x 32 cols within a strip
    const int wm = (wid & 1) * 64;
    const int wn = (wid >> 1) * 32;

    const float*  A32 = X   + ((size_t)b * SEQ + row0) * HID;
    const __half* Bg  = g_B + (size_t)b * HID * HID;
    float*        C   = Y   + ((size_t)b * SEQ + row0) * HID;

    float acc[4][4][4];
#pragma unroll
    for (int i = 0; i < 4; i++)
#pragma unroll
        for (int j = 0; j < 4; j++)
#pragma unroll
            for (int q = 0; q < 4; q++) acc[i][j][q] = 0.f;

    // B loader: chunk j -> col strip (j>>2)*128, k (j&3)*64
    const int blr = tid >> 3, blc = tid & 7;
#define ISSUE_B(j)                                                              \
    do {                                                                        \
        const uint32_t st = sb + OFF_B + (uint32_t)((j) & 1) * 16384;           \
        const __half* bp = Bg + (size_t)(((j) >> 2) * 128) * HID + ((j) & 3) * 64; \
        _Pragma("unroll")                                                       \
        for (int i = 0; i < 4; i++) {                                           \
            int r = blr + i * 32;                                               \
            cp_async16(st + sw_off(r, blc * 8), &bp[(size_t)r * HID + blc * 8]); \
        }                                                                       \
        CP_COMMIT();                                                            \
    } while (0)

#define COMPUTE(j)                                                              \
    do {                                                                        \
        const uint32_t aoff = sb + OFF_A + (uint32_t)((j) & 3) * 16384;         \
        const uint32_t boff = sb + OFF_B + (uint32_t)((j) & 1) * 16384;         \
        _Pragma("unroll")                                                       \
        for (int s = 0; s < 4; s++) {                                           \
            uint32_t ah[4][4], bb[2][4];                                        \
            const int arow = wm + (lane & 15);                                  \
            const int akk  = s * 16 + ((lane >> 4) << 3);                       \
            _Pragma("unroll")                                                   \
            for (int mi = 0; mi < 4; mi++)                                      \
                ldmx4(aoff + sw_off(arow + mi * 16, akk), ah[mi]);              \
            const int bm  = lane >> 3;                                          \
            const int brq = ((bm >> 1) << 3) + (lane & 7);                      \
            const int bkq = s * 16 + ((bm & 1) << 3);                           \
            _Pragma("unroll")                                                   \
            for (int p = 0; p < 2; p++)                                         \
                ldmx4(boff + sw_off(wn + p * 16 + brq, bkq), bb[p]);            \
            _Pragma("unroll")                                                   \
            for (int mi = 0; mi < 4; mi++)                                      \
                _Pragma("unroll")                                               \
                for (int p = 0; p < 2; p++) {                                   \
                    mma16816(acc[mi][p * 2 + 0], ah[mi], &bb[p][0]);            \
                    mma16816(acc[mi][p * 2 + 1], ah[mi], &bb[p][2]);            \
                }                                                               \
        }                                                                       \
    } while (0)

#define EPILOGUE(strip)                                                         \
    do {                                                                        \
        float* Ct = C + (strip) * 128;                                          \
        _Pragma("unroll")                                                       \
        for (int mi = 0; mi < 4; mi++) {                                        \
            int r0 = wm + mi * 16 + (lane >> 2);                                \
            _Pragma("unroll")                                                   \
            for (int nj = 0; nj < 4; nj++) {                                    \
                int cc = wn + nj * 8 + (lane & 3) * 2;                          \
                *(float2*)&Ct[(size_t)r0 * HID + cc] =                          \
                    make_float2(acc[mi][nj][0], acc[mi][nj][1]);                \
                *(float2*)&Ct[(size_t)(r0 + 8) * HID + cc] =                    \
                    make_float2(acc[mi][nj][2], acc[mi][nj][3]);                \
                acc[mi][nj][0] = acc[mi][nj][1] = 0.f;                          \
                acc[mi][nj][2] = acc[mi][nj][3] = 0.f;                          \
            }                                                                   \
        }                                                                       \
    } while (0)

    // ---- prologue: B chunk 0 in flight, then convert whole A panel (x1 read)
    ISSUE_B(0);
    {
        const int row = tid >> 1;
        const int kq  = (tid & 1) * 32;
#pragma unroll
        for (int c = 0; c < 4; c++) {
            const float* ap = A32 + (size_t)row * HID + c * 64 + kq;
            float4 v[8];
#pragma unroll
            for (int i = 0; i < 8; i++) v[i] = *(const float4*)&ap[i * 4];
#pragma unroll
            for (int i = 0; i < 8; i++) {
                __half2 h01 = __floats2half2_rn(v[i].x, v[i].y);
                __half2 h23 = __floats2half2_rn(v[i].z, v[i].w);
                uint2 p; p.x = *(uint32_t*)&h01; p.y = *(uint32_t*)&h23;
                *(uint2*)(smem + OFF_A + c * 16384 + sw_off(row, kq + i * 4)) = p;
            }
        }
    }

    // ---- 8-chunk pipeline: iter j issues j+1, waits for j, computes j
#pragma unroll
    for (int j = 0; j < 8; j++) {
        if (j + 1 < 8) { ISSUE_B(j + 1); CP_WAIT(1); }
        else          { CP_WAIT(0); }
        __syncthreads();
        COMPUTE(j);
        if (j == 3) EPILOGUE(0);
        __syncthreads();
    }
    EPILOGUE(1);

#undef ISSUE_B
#undef COMPUTE
#undef EPILOGUE
}

// ===========================================================================
extern "C" void kernel_launch(void* const* d_in, const int* in_sizes, int n_in,
                              void* d_out, int out_size) {
    const float* x     = (const float*)d_in[0];  // [8, 4096, 256]
    const float* t     = (const float*)d_in[1];  // [8, 1]
    const float* osc   = (const float*)d_in[2];  // [6, 256, 256]
    const float* phase = (const float*)d_in[3];  // [6, 256]
    float* out = (float*)d_out;                  // [8, 4096, 256]
    (void)in_sizes; (void)n_in; (void)out_size;

    cudaFuncSetAttribute(gemm_kernel, cudaFuncAttributeMaxDynamicSharedMemorySize, SMEM_TOTAL);

    build_M_kernel<<<dim3(32, BATCH), 256>>>(osc, phase, t);
    gemm_kernel<<<dim3(SEQ / 128, BATCH), 256, SMEM_TOTAL>>>(x, out);
}